// round 9
// baseline (speedup 1.0000x reference)
#include <cuda_runtime.h>
#include <math.h>

// ---------------- problem constants ----------------
#define NTOT   22743
#define N0     1083
#define N1     4332
#define N2     17328
#define OFF1   1083
#define OFF2   5415
#define BATCH  8
#define TOPK   1000
#define NCAND  3000
#define MAXDET 100
#define IMGMAX 607
#define SORTN  4096
#define MIN_SC 0.05f

// ---------------- device scratch ----------------
__device__ float g_score[BATCH * NTOT];
__device__ int   g_cls[BATCH * NTOT];
// packed candidate key: score_bits<<32 | (4095-slot)<<15 | anchor_n
__device__ unsigned long long g_ckey[BATCH * NCAND];

__device__ __forceinline__ float sigm(float x) { return 1.0f / (1.0f + expf(-x)); }

// ---------------- stage 1: decode scores only (4 threads / anchor) ----------------
__global__ void decode_kernel(
    const float* __restrict__ obj0, const float* __restrict__ cls0,
    const float* __restrict__ obj1, const float* __restrict__ cls1,
    const float* __restrict__ obj2, const float* __restrict__ cls2)
{
    int t = blockIdx.x * blockDim.x + threadIdx.x;
    int a = t >> 2;
    int sub = t & 3;
    if (a >= BATCH * NTOT) a = BATCH * NTOT - 1;   // duplicates write identical data
    int b = a / NTOT;
    int n = a - b * NTOT;

    const float *obj, *cls;
    int local, cnt;
    if (n < N0)        { obj = obj0; cls = cls0; local = n;        cnt = N0; }
    else if (n < OFF2) { obj = obj1; cls = cls1; local = n - OFF1; cnt = N1; }
    else               { obj = obj2; cls = cls2; local = n - OFF2; cnt = N2; }

    size_t base = (size_t)b * cnt + local;

    const float4* cp4 = reinterpret_cast<const float4*>(cls + base * 80) + sub * 5;
    float v[20];
    {
        float4 q0 = __ldg(cp4);
        float4 q1 = __ldg(cp4 + 1);
        float4 q2 = __ldg(cp4 + 2);
        float4 q3 = __ldg(cp4 + 3);
        float4 q4 = __ldg(cp4 + 4);
        v[0]=q0.x; v[1]=q0.y; v[2]=q0.z; v[3]=q0.w;
        v[4]=q1.x; v[5]=q1.y; v[6]=q1.z; v[7]=q1.w;
        v[8]=q2.x; v[9]=q2.y; v[10]=q2.z; v[11]=q2.w;
        v[12]=q3.x; v[13]=q3.y; v[14]=q3.z; v[15]=q3.w;
        v[16]=q4.x; v[17]=q4.y; v[18]=q4.z; v[19]=q4.w;
    }
    float m01 = fmaxf(v[0], v[1]),   m23 = fmaxf(v[2], v[3]);
    float m45 = fmaxf(v[4], v[5]),   m67 = fmaxf(v[6], v[7]);
    float m89 = fmaxf(v[8], v[9]),   mAB = fmaxf(v[10], v[11]);
    float mCD = fmaxf(v[12], v[13]), mEF = fmaxf(v[14], v[15]);
    float mGH = fmaxf(v[16], v[17]), mIJ = fmaxf(v[18], v[19]);
    float a0 = fmaxf(m01, m23), a1 = fmaxf(m45, m67), a2 = fmaxf(m89, mAB);
    float a3 = fmaxf(mCD, mEF), a4 = fmaxf(mGH, mIJ);
    float best = fmaxf(fmaxf(fmaxf(a0, a1), fmaxf(a2, a3)), a4);
    int bi = 19;
#pragma unroll
    for (int j = 18; j >= 0; --j) bi = (v[j] == best) ? j : bi;
    bi += sub * 20;

#pragma unroll
    for (int off = 1; off <= 2; off <<= 1) {
        float ov = __shfl_xor_sync(0xffffffffu, best, off);
        int   oi = __shfl_xor_sync(0xffffffffu, bi, off);
        if (ov > best || (ov == best && oi < bi)) { best = ov; bi = oi; }
    }

    if (sub == 0) {
        float o = sigm(__ldg(obj + base));
        g_score[a] = sigm(best) * o;
        g_cls[a]   = bi;
    }
}

// ---------------- stage 2: top-1000, tri-mid binary search (2 bits / 2 barriers per iter) ----
#define TKT 512
#define PER 34   // ceil(17328/512)

__global__ void __launch_bounds__(TKT) topk_kernel()
{
    int level = blockIdx.x, b = blockIdx.y;
    int offs = (level == 0) ? 0  : ((level == 1) ? OFF1 : OFF2);
    int cnt  = (level == 0) ? N0 : ((level == 1) ? N1  : N2);
    const unsigned* sc = reinterpret_cast<const unsigned*>(g_score + b * NTOT + offs);

    int tid = threadIdx.x;
    int lane = tid & 31, warp = tid >> 5;

    unsigned v[PER];
#pragma unroll
    for (int k = 0; k < PER; ++k) {
        int i = tid + (k << 9);
        v[k] = (i < cnt) ? __ldg(sc + i) : 0u;
    }

    __shared__ unsigned wr1[16], wr2[16], wr3[16];
    __shared__ unsigned wred[16];
    __shared__ unsigned sb[2];
    __shared__ int s_found;
    if (tid == 0) { sb[0] = 0u; sb[1] = 0x3F800000u; }
    __syncthreads();

    // find minimal tau with count(bits > tau) < TOPK (tau = bits of k-th largest)
    for (;;) {
        unsigned lo = sb[0], hi = sb[1];
        if (lo >= hi) break;
        unsigned q = (hi - lo) >> 2;
        unsigned m1 = lo + q, m2 = m1 + q, m3 = m2 + q;
        unsigned c1 = 0, c2 = 0, c3 = 0;
#pragma unroll
        for (int k = 0; k < PER; ++k) {
            c1 += (v[k] > m1) ? 1u : 0u;
            c2 += (v[k] > m2) ? 1u : 0u;
            c3 += (v[k] > m3) ? 1u : 0u;
        }
#pragma unroll
        for (int o = 16; o; o >>= 1) {
            c1 += __shfl_down_sync(0xffffffffu, c1, o);
            c2 += __shfl_down_sync(0xffffffffu, c2, o);
            c3 += __shfl_down_sync(0xffffffffu, c3, o);
        }
        if (lane == 0) { wr1[warp] = c1; wr2[warp] = c2; wr3[warp] = c3; }
        __syncthreads();
        if (tid < 32) {
            unsigned s1 = (tid < 16) ? wr1[tid] : 0u;
            unsigned s2 = (tid < 16) ? wr2[tid] : 0u;
            unsigned s3 = (tid < 16) ? wr3[tid] : 0u;
#pragma unroll
            for (int o = 8; o; o >>= 1) {
                s1 += __shfl_down_sync(0xffffffffu, s1, o);
                s2 += __shfl_down_sync(0xffffffffu, s2, o);
                s3 += __shfl_down_sync(0xffffffffu, s3, o);
            }
            if (tid == 0) {
                if      (s1 < (unsigned)TOPK) sb[1] = m1;
                else if (s2 < (unsigned)TOPK) { sb[0] = m1 + 1u; sb[1] = m2; }
                else if (s3 < (unsigned)TOPK) { sb[0] = m2 + 1u; sb[1] = m3; }
                else                          sb[0] = m3 + 1u;
            }
        }
        __syncthreads();
    }
    unsigned tau = sb[0];

    // exclusive scan of per-thread strictly-greater counts
    unsigned c = 0;
#pragma unroll
    for (int k = 0; k < PER; ++k) c += (v[k] > tau) ? 1u : 0u;
    unsigned ws = c;
#pragma unroll
    for (int o = 1; o < 32; o <<= 1) {
        unsigned nb = __shfl_up_sync(0xffffffffu, ws, o);
        if (lane >= o) ws += nb;
    }
    if (lane == 31) wred[warp] = ws;
    __syncthreads();
    if (tid < 32) {
        unsigned s2 = (tid < 16) ? wred[tid] : 0u;
#pragma unroll
        for (int o = 1; o < 16; o <<= 1) {
            unsigned nb = __shfl_up_sync(0xffffffffu, s2, o);
            if (lane >= o) s2 += nb;
        }
        if (tid < 16) wred[tid] = s2;
    }
    __syncthreads();
    unsigned excl = ws - c + (warp ? wred[warp - 1] : 0u);
    unsigned mtot = wred[15];          // total strictly greater (< TOPK)

    unsigned pos = excl;
#pragma unroll
    for (int k = 0; k < PER; ++k) {
        int i = tid + (k << 9);
        if (i < cnt && v[k] > tau) {
            unsigned slot = (unsigned)(level * TOPK) + pos;
            unsigned low  = ((4095u - slot) << 15) | (unsigned)(offs + i);
            g_ckey[b * NCAND + slot] = ((unsigned long long)v[k] << 32) | low;
            pos++;
        }
    }
    __syncthreads();

    // fill remaining slots with == tau entries, ascending index (top_k tie rule)
    int r = TOPK - (int)mtot;
    int last = -1;
    for (int rep = 0; rep < r; ++rep) {
        unsigned lm = 0xFFFFFFFFu;
#pragma unroll
        for (int k = 0; k < PER; ++k) {
            int i = tid + (k << 9);
            if (i < cnt && i > last && v[k] == tau) lm = min(lm, (unsigned)i);
        }
#pragma unroll
        for (int o = 16; o; o >>= 1) lm = min(lm, __shfl_down_sync(0xffffffffu, lm, o));
        if (lane == 0) wred[warp] = lm;
        __syncthreads();
        if (tid < 32) {
            unsigned s2 = (tid < 16) ? wred[tid] : 0xFFFFFFFFu;
#pragma unroll
            for (int o = 8; o; o >>= 1) s2 = min(s2, __shfl_down_sync(0xffffffffu, s2, o));
            if (tid == 0) s_found = (int)s2;
        }
        __syncthreads();
        int found = s_found;
        if (tid == 0 && found >= 0 && found < cnt) {
            unsigned slot = (unsigned)(level * TOPK + (int)mtot + rep);
            unsigned low  = ((4095u - slot) << 15) | (unsigned)(offs + found);
            g_ckey[b * NCAND + slot] = ((unsigned long long)tau << 32) | low;
        }
        last = found;
        __syncthreads();
    }
}

// ---------------- stage 3: bitonic sort + flat greedy NMS (dynamic smem) ----------------
// dynamic smem layout (bytes):
//   [0, 24576)       u64 keys[3072]          sorted keys (persist)
//   [24576, 61440)   union: u64 sk[4096] (sort exchange, 32KB)
//                       OR  int cA[3072] | cB[3072] | car[3072] (boxes, 36KB)
//   [61440, 64512)   u32 alive4[768]         1 byte per candidate
//   [64512, 66512)   kp1/kp2/kar/kn int[100] + ksc float[100]
#define DSMEM 66560

__device__ __forceinline__ unsigned long long u64max(unsigned long long a, unsigned long long b) { return a > b ? a : b; }
__device__ __forceinline__ unsigned long long u64min(unsigned long long a, unsigned long long b) { return a < b ? a : b; }
__device__ __forceinline__ void cswap(unsigned long long& a, unsigned long long& b, bool desc)
{
    if (desc ? (a < b) : (a > b)) { unsigned long long t = a; a = b; b = t; }
}

__global__ void __launch_bounds__(1024) sortnms_kernel(
    const float* __restrict__ reg0, const float* __restrict__ anc0,
    const float* __restrict__ reg1, const float* __restrict__ anc1,
    const float* __restrict__ reg2, const float* __restrict__ anc2,
    float* __restrict__ out)
{
    int b = blockIdx.x;
    int tid = threadIdx.x;
    int i0 = tid << 2;

    extern __shared__ __align__(16) unsigned char dsm[];
    unsigned long long* keys = reinterpret_cast<unsigned long long*>(dsm);
    unsigned long long* sk   = reinterpret_cast<unsigned long long*>(dsm + 24576);
    int* cA  = reinterpret_cast<int*>(dsm + 24576);
    int* cB  = reinterpret_cast<int*>(dsm + 24576 + 12288);
    int* car = reinterpret_cast<int*>(dsm + 24576 + 24576);
    unsigned* alive4 = reinterpret_cast<unsigned*>(dsm + 61440);
    int* kp1 = reinterpret_cast<int*>(dsm + 64512);
    int* kp2 = kp1 + 100;
    int* kar = kp1 + 200;
    int* kn  = kp1 + 300;
    float* ksc = reinterpret_cast<float*>(kp1 + 400);

    __shared__ unsigned swred[32];
    __shared__ int s_V, s_idx, s_kept;

    // ---- load packed keys ----
    unsigned long long r[4];
#pragma unroll
    for (int s = 0; s < 4; ++s) {
        int i = i0 + s;
        r[s] = (i < NCAND) ? __ldg(g_ckey + b * NCAND + i) : 0ull;
    }
    __syncthreads();

    // ---- bitonic sort (descending), 4 elems/thread ----
    for (int k = 2; k <= SORTN; k <<= 1) {
        for (int j = k >> 1; j > 0; j >>= 1) {
            if (j >= 128) {
                sk[i0] = r[0]; sk[i0 + 1] = r[1]; sk[i0 + 2] = r[2]; sk[i0 + 3] = r[3];
                __syncthreads();
                int pb = i0 ^ j;
                bool takeMax = (((i0 & k) == 0) != ((i0 & j) != 0));
#pragma unroll
                for (int s = 0; s < 4; ++s) {
                    unsigned long long p = sk[pb + s];
                    r[s] = takeMax ? u64max(r[s], p) : u64min(r[s], p);
                }
                __syncthreads();
            } else if (j >= 4) {
                int lx = j >> 2;
                bool takeMax = (((i0 & k) == 0) != ((i0 & j) != 0));
#pragma unroll
                for (int s = 0; s < 4; ++s) {
                    unsigned long long p = __shfl_xor_sync(0xffffffffu, r[s], lx);
                    r[s] = takeMax ? u64max(r[s], p) : u64min(r[s], p);
                }
            } else if (j == 2) {
                cswap(r[0], r[2], ((i0    ) & k) == 0);
                cswap(r[1], r[3], ((i0 + 1) & k) == 0);
            } else {
                cswap(r[0], r[1], ((i0    ) & k) == 0);
                cswap(r[2], r[3], ((i0 + 2) & k) == 0);
            }
        }
    }
    // sk no longer read by anyone past the last smem stage's barrier.

    // ---- persist sorted keys; decode all candidate boxes once ----
    int pvalid = 0;
#pragma unroll
    for (int s = 0; s < 4; ++s) {
        int rank = i0 + s;
        if (rank < 3072) {
            keys[rank] = r[s];
            float sc = __uint_as_float((unsigned)(r[s] >> 32));
            if (sc > MIN_SC) {
                pvalid++;
                int n = (int)((unsigned)r[s] & 0x7FFFu);
                const float *reg, *anc;
                int local, cnt;
                if (n < N0)        { reg = reg0; anc = anc0; local = n;        cnt = N0; }
                else if (n < OFF2) { reg = reg1; anc = anc1; local = n - OFF1; cnt = N1; }
                else               { reg = reg2; anc = anc2; local = n - OFF2; cnt = N2; }
                size_t base = (size_t)b * cnt + local;

                float4 rg = __ldg(reinterpret_cast<const float4*>(reg + base * 4));
                const float* ap = anc + base * 5;
                float ax = __ldg(ap),     ay = __ldg(ap + 1);
                float aw = __ldg(ap + 2), ah = __ldg(ap + 3);
                float st = __ldg(ap + 4);

                float cx = __fmul_rn(__fadd_rn(sigm(rg.x), ax), st);
                float cy = __fmul_rn(__fadd_rn(sigm(rg.y), ay), st);
                float w  = __fdiv_rn(__fmul_rn(expf(rg.z), aw), st);
                float h  = __fdiv_rn(__fmul_rn(expf(rg.w), ah), st);
                float x1 = __fsub_rn(cx, __fmul_rn(0.5f, w));
                float y1 = __fsub_rn(cy, __fmul_rn(0.5f, h));
                float x2 = __fadd_rn(w, x1);
                float y2 = __fadd_rn(h, y1);

                int xi1 = max((int)x1, 0);
                int yi1 = max((int)y1, 0);
                int xi2 = min((int)x2, IMGMAX);
                int yi2 = min((int)y2, IMGMAX);

                cA[rank]  = xi1 | (yi1 << 16);
                cB[rank]  = xi2 | (yi2 << 16);
                car[rank] = (xi2 - xi1) * (yi2 - yi1);
            }
        }
    }

    // ---- V = number of valid (score > 0.05) candidates (a prefix of sorted order) ----
    unsigned pc = (unsigned)pvalid;
#pragma unroll
    for (int o = 16; o; o >>= 1) pc += __shfl_down_sync(0xffffffffu, pc, o);
    if ((tid & 31) == 0) swred[tid >> 5] = pc;
    __syncthreads();
    if (tid < 32) {
        unsigned s2 = swred[tid];
#pragma unroll
        for (int o = 16; o; o >>= 1) s2 += __shfl_down_sync(0xffffffffu, s2, o);
        if (tid == 0) s_V = (int)s2;
    }
    __syncthreads();
    int V = s_V;

    // ---- alive bytes: 1 byte per candidate, rank < V ----
    if (tid < 768) {
        int base = tid << 2;
        unsigned w = 0;
#pragma unroll
        for (int s = 0; s < 4; ++s)
            if (base + s < V) w |= (1u << (8 * s));
        alive4[tid] = w;
    }
    __syncthreads();

    // ---- flat greedy NMS: 2 barriers per kept box ----
    int kept = 0;    // maintained by tid 0
    int curw = 0;
    for (;;) {
        if (tid == 0) {
            int idx = -1;
            while (curw < 768) {
                unsigned w = alive4[curw];
                if (w) { idx = (curw << 2) + ((__ffs(w) - 1) >> 3); break; }
                curw++;
            }
            if (idx < 0) {
                s_idx = -1;
            } else {
                alive4[curw] &= ~(0xFFu << (((unsigned)idx & 3u) * 8u));
                kp1[kept] = cA[idx]; kp2[kept] = cB[idx]; kar[kept] = car[idx];
                unsigned long long key = keys[idx];
                ksc[kept] = __uint_as_float((unsigned)(key >> 32));
                kn[kept]  = (int)((unsigned)key & 0x7FFFu);
                kept++;
                s_idx = (kept >= MAXDET) ? -1 : idx;
            }
            s_kept = kept;
        }
        __syncthreads();
        int idx = s_idx;
        if (idx < 0) break;

        // parallel suppression of all alive candidates vs the kept box
        if (tid < 768) {
            unsigned w = alive4[tid];
            if (w) {
                int p1 = cA[idx], p2 = cB[idx], par = car[idx];   // broadcast
                int px1 = p1 & 0xFFFF, py1 = p1 >> 16;
                int px2 = p2 & 0xFFFF, py2 = p2 >> 16;
                int4 qa = reinterpret_cast<int4*>(cA)[tid];
                int4 qb = reinterpret_cast<int4*>(cB)[tid];
                int4 qr = reinterpret_cast<int4*>(car)[tid];
                int aa[4] = { qa.x, qa.y, qa.z, qa.w };
                int bb[4] = { qb.x, qb.y, qb.z, qb.w };
                int rr[4] = { qr.x, qr.y, qr.z, qr.w };
#pragma unroll
                for (int s = 0; s < 4; ++s) {
                    if ((w >> (8 * s)) & 1u) {
                        int iw = min(px2, bb[s] & 0xFFFF) - max(px1, aa[s] & 0xFFFF);
                        int ih = min(py2, bb[s] >> 16)    - max(py1, aa[s] >> 16);
                        if (iw > 0 && ih > 0) {
                            int inter = iw * ih;
                            // exact int equivalent of iou > 0.5 (all quantities exact ints)
                            if (3 * inter > par + rr[s]) w &= ~(0xFFu << (8 * s));
                        }
                    }
                }
                alive4[tid] = w;
            }
        }
        __syncthreads();
    }
    __syncthreads();

    // ---- outputs (parallel) ----
    int nk = s_kept;
    const int* gcls = g_cls + b * NTOT;
    for (int k = tid; k < MAXDET; k += 1024) {
        float osc = -1.0f, ocl = -1.0f, ox1 = -1.0f, oy1 = -1.0f, ox2 = -1.0f, oy2 = -1.0f;
        if (k < nk) {
            osc = ksc[k];
            ocl = (float)__ldg(gcls + kn[k]);
            int p1 = kp1[k], p2 = kp2[k];
            ox1 = (float)(p1 & 0xFFFF); oy1 = (float)(p1 >> 16);
            ox2 = (float)(p2 & 0xFFFF); oy2 = (float)(p2 >> 16);
        }
        out[b * MAXDET + k] = osc;
        out[BATCH * MAXDET + b * MAXDET + k] = ocl;
        int ob = 2 * BATCH * MAXDET + (b * MAXDET + k) * 4;
        out[ob] = ox1; out[ob + 1] = oy1; out[ob + 2] = ox2; out[ob + 3] = oy2;
    }
}

// ---------------- launcher ----------------
extern "C" void kernel_launch(void* const* d_in, const int* in_sizes, int n_in,
                              void* d_out, int out_size)
{
    (void)out_size;
    static const int dictSizes[12] = {  8664,  34656,   693120,  43320,
                                       34656, 138624,  2772480, 173280,
                                      138624, 554496, 11089920, 693120 };
    static const int sigSizes[12]  = {  8664,  34656, 138624,
                                       34656, 138624, 554496,
                                      693120, 2772480, 11089920,
                                       43320, 173280, 693120 };
    bool isDict = (n_in >= 12), isSig = (n_in >= 12);
    for (int i = 0; i < 12 && i < n_in; i++) {
        if (in_sizes[i] != dictSizes[i]) isDict = false;
        if (in_sizes[i] != sigSizes[i])  isSig  = false;
    }

    // canonical: [0..2]=obj, [3..5]=reg, [6..8]=cls, [9..11]=anchors
    const float* in[12];
    if (isSig && !isDict) {
        for (int i = 0; i < 12; i++) in[i] = (const float*)d_in[i];
    } else {
        for (int l = 0; l < 3; l++) {
            in[l]     = (const float*)d_in[4 * l + 0];
            in[3 + l] = (const float*)d_in[4 * l + 1];
            in[6 + l] = (const float*)d_in[4 * l + 2];
            in[9 + l] = (const float*)d_in[4 * l + 3];
        }
    }

    cudaFuncSetAttribute(sortnms_kernel,
                         cudaFuncAttributeMaxDynamicSharedMemorySize, DSMEM);

    int nthreads = BATCH * NTOT * 4;
    decode_kernel<<<(nthreads + 255) / 256, 256>>>(
        in[0], in[6], in[1], in[7], in[2], in[8]);

    dim3 g2(3, BATCH);
    topk_kernel<<<g2, TKT>>>();

    sortnms_kernel<<<BATCH, 1024, DSMEM>>>(in[3], in[9], in[4], in[10], in[5], in[11],
                                           (float*)d_out);
}

// round 11
// speedup vs baseline: 1.1897x; 1.1897x over previous
#include <cuda_runtime.h>
#include <math.h>

// ---------------- problem constants ----------------
#define NTOT   22743
#define N0     1083
#define N1     4332
#define N2     17328
#define OFF1   1083
#define OFF2   5415
#define BATCH  8
#define TOPK   1000
#define NCAND  3000
#define MAXDET 100
#define IMGMAX 607
#define SORTN  4096
#define CH     512
#define CW     16
#define MIN_SC 0.05f

#define NBAR(id, cnt) asm volatile("bar.sync %0, %1;" :: "r"(id), "r"(cnt) : "memory")

// ---------------- device scratch ----------------
__device__ float g_score[BATCH * NTOT];
__device__ int   g_cls[BATCH * NTOT];

__device__ __forceinline__ float sigm(float x) { return 1.0f / (1.0f + expf(-x)); }

// ---------------- stage 1: decode scores only (4 threads / anchor) ----------------
__global__ void decode_kernel(
    const float* __restrict__ obj0, const float* __restrict__ cls0,
    const float* __restrict__ obj1, const float* __restrict__ cls1,
    const float* __restrict__ obj2, const float* __restrict__ cls2)
{
    int t = blockIdx.x * blockDim.x + threadIdx.x;
    int a = t >> 2;
    int sub = t & 3;
    if (a >= BATCH * NTOT) a = BATCH * NTOT - 1;   // duplicates write identical data
    int b = a / NTOT;
    int n = a - b * NTOT;

    const float *obj, *cls;
    int local, cnt;
    if (n < N0)        { obj = obj0; cls = cls0; local = n;        cnt = N0; }
    else if (n < OFF2) { obj = obj1; cls = cls1; local = n - OFF1; cnt = N1; }
    else               { obj = obj2; cls = cls2; local = n - OFF2; cnt = N2; }

    size_t base = (size_t)b * cnt + local;

    const float4* cp4 = reinterpret_cast<const float4*>(cls + base * 80) + sub * 5;
    float v[20];
    {
        float4 q0 = __ldg(cp4);
        float4 q1 = __ldg(cp4 + 1);
        float4 q2 = __ldg(cp4 + 2);
        float4 q3 = __ldg(cp4 + 3);
        float4 q4 = __ldg(cp4 + 4);
        v[0]=q0.x; v[1]=q0.y; v[2]=q0.z; v[3]=q0.w;
        v[4]=q1.x; v[5]=q1.y; v[6]=q1.z; v[7]=q1.w;
        v[8]=q2.x; v[9]=q2.y; v[10]=q2.z; v[11]=q2.w;
        v[12]=q3.x; v[13]=q3.y; v[14]=q3.z; v[15]=q3.w;
        v[16]=q4.x; v[17]=q4.y; v[18]=q4.z; v[19]=q4.w;
    }
    float m01 = fmaxf(v[0], v[1]),   m23 = fmaxf(v[2], v[3]);
    float m45 = fmaxf(v[4], v[5]),   m67 = fmaxf(v[6], v[7]);
    float m89 = fmaxf(v[8], v[9]),   mAB = fmaxf(v[10], v[11]);
    float mCD = fmaxf(v[12], v[13]), mEF = fmaxf(v[14], v[15]);
    float mGH = fmaxf(v[16], v[17]), mIJ = fmaxf(v[18], v[19]);
    float a0 = fmaxf(m01, m23), a1 = fmaxf(m45, m67), a2 = fmaxf(m89, mAB);
    float a3 = fmaxf(mCD, mEF), a4 = fmaxf(mGH, mIJ);
    float best = fmaxf(fmaxf(fmaxf(a0, a1), fmaxf(a2, a3)), a4);
    int bi = 19;
#pragma unroll
    for (int j = 18; j >= 0; --j) bi = (v[j] == best) ? j : bi;
    bi += sub * 20;

#pragma unroll
    for (int off = 1; off <= 2; off <<= 1) {
        float ov = __shfl_xor_sync(0xffffffffu, best, off);
        int   oi = __shfl_xor_sync(0xffffffffu, bi, off);
        if (ov > best || (ov == best && oi < bi)) { best = ov; bi = oi; }
    }

    if (sub == 0) {
        float o = sigm(__ldg(obj + base));
        g_score[a] = sigm(best) * o;
        g_cls[a]   = bi;
    }
}

// ---------------- stage 2: fused topk (warp-specialized) + sort + NMS ----------------
// dynamic smem: u64[4096] = 32KB; serves as keys / sort workspace / M matrix
#define DSMEM 32768

__device__ __forceinline__ unsigned long long u64max(unsigned long long a, unsigned long long b) { return a > b ? a : b; }
__device__ __forceinline__ unsigned long long u64min(unsigned long long a, unsigned long long b) { return a < b ? a : b; }
__device__ __forceinline__ void cswap(unsigned long long& a, unsigned long long& b, bool desc)
{
    if (desc ? (a < b) : (a > b)) { unsigned long long t = a; a = b; b = t; }
}

__global__ void __launch_bounds__(1024) topk_sortnms_kernel(
    const float* __restrict__ reg0, const float* __restrict__ anc0,
    const float* __restrict__ reg1, const float* __restrict__ anc1,
    const float* __restrict__ reg2, const float* __restrict__ anc2,
    float* __restrict__ out)
{
    int b = blockIdx.x;
    int tid = threadIdx.x;
    int lane = tid & 31, gw = tid >> 5;

    extern __shared__ __align__(16) unsigned char dsm[];
    unsigned long long* keys = reinterpret_cast<unsigned long long*>(dsm);  // [4096]
    unsigned long long* sk   = keys;                                        // sort ws
    unsigned* Mw = reinterpret_cast<unsigned*>(dsm);                        // M[512][16]

    __shared__ unsigned red1[32], red2[32], red3[32];
    __shared__ unsigned sLo[3], sHi[3], sF[3];
    __shared__ unsigned long long ckey[CH];
    __shared__ int cx1[CH], cy1[CH], cx2[CH], cy2[CH];
    __shared__ unsigned supv[CW], limw[CW];
    __shared__ int kp1[MAXDET], kp2[MAXDET], kn[MAXDET];
    __shared__ float ksc[MAXDET];
    __shared__ int s_kept, s_done, s_limit;

    if (tid == 0) { s_kept = 0; s_done = 0; }
    // zero pad region of keys (ranks 3000..4095); visible after the big __syncthreads
    for (int idx = 3000 + tid; idx < SORTN; idx += 1024) keys[idx] = 0ull;

    // ======== PHASE A: per-level top-1000, warp-specialized partitions ========
    int L, pbw, pwarps, offs, cnt, per, barid;
    if (gw < 24)      { L = 2; pbw = 0;  pwarps = 24; offs = OFF2; cnt = N2; per = 23; barid = 1; }
    else if (gw < 30) { L = 1; pbw = 24; pwarps = 6;  offs = OFF1; cnt = N1; per = 23; barid = 2; }
    else              { L = 0; pbw = 30; pwarps = 2;  offs = 0;    cnt = N0; per = 17; barid = 3; }
    int pthreads = pwarps << 5;
    int ptid = tid - (pbw << 5);

    const unsigned* sc = reinterpret_cast<const unsigned*>(g_score + b * NTOT + offs);
    unsigned v[23];
#pragma unroll
    for (int k = 0; k < 23; ++k) {
        int i = ptid + k * pthreads;
        v[k] = (k < per && i < cnt) ? __ldg(sc + i) : 0u;
    }

    if (ptid == 0) { sLo[L] = 0u; sHi[L] = 0x3F800000u; }
    NBAR(barid, pthreads);

    // tri-mid search: minimal tau with count(bits > tau) < TOPK
    for (int it = 0; it < 20; ++it) {
        unsigned lo = sLo[L], hi = sHi[L];
        unsigned c1 = 0, c2 = 0, c3 = 0, m1 = 0, m2 = 0, m3 = 0;
        if (lo < hi) {
            unsigned q = (hi - lo) >> 2;
            m1 = lo + q; m2 = m1 + q; m3 = m2 + q;
#pragma unroll
            for (int k = 0; k < 23; ++k) {
                if (k < per) {
                    c1 += (v[k] > m1) ? 1u : 0u;
                    c2 += (v[k] > m2) ? 1u : 0u;
                    c3 += (v[k] > m3) ? 1u : 0u;
                }
            }
#pragma unroll
            for (int o = 16; o; o >>= 1) {
                c1 += __shfl_down_sync(0xffffffffu, c1, o);
                c2 += __shfl_down_sync(0xffffffffu, c2, o);
                c3 += __shfl_down_sync(0xffffffffu, c3, o);
            }
        }
        if (lane == 0) { red1[gw] = c1; red2[gw] = c2; red3[gw] = c3; }
        NBAR(barid, pthreads);
        if (gw == pbw && lo < hi) {
            unsigned s1 = (lane < pwarps) ? red1[pbw + lane] : 0u;
            unsigned s2 = (lane < pwarps) ? red2[pbw + lane] : 0u;
            unsigned s3 = (lane < pwarps) ? red3[pbw + lane] : 0u;
#pragma unroll
            for (int o = 16; o; o >>= 1) {
                s1 += __shfl_down_sync(0xffffffffu, s1, o);
                s2 += __shfl_down_sync(0xffffffffu, s2, o);
                s3 += __shfl_down_sync(0xffffffffu, s3, o);
            }
            if (lane == 0) {
                if      (s1 < (unsigned)TOPK) sHi[L] = m1;
                else if (s2 < (unsigned)TOPK) { sLo[L] = m1 + 1u; sHi[L] = m2; }
                else if (s3 < (unsigned)TOPK) { sLo[L] = m2 + 1u; sHi[L] = m3; }
                else                          sLo[L] = m3 + 1u;
            }
        }
        NBAR(barid, pthreads);
    }
    unsigned tau = sLo[L];

    // partition-wide exclusive scan of strictly-greater counts
    unsigned c = 0;
#pragma unroll
    for (int k = 0; k < 23; ++k) if (k < per) c += (v[k] > tau) ? 1u : 0u;
    unsigned ws = c;
#pragma unroll
    for (int o = 1; o < 32; o <<= 1) {
        unsigned nb = __shfl_up_sync(0xffffffffu, ws, o);
        if (lane >= o) ws += nb;
    }
    if (lane == 31) red1[gw] = ws;
    NBAR(barid, pthreads);
    if (gw == pbw) {
        unsigned x = (lane < pwarps) ? red1[pbw + lane] : 0u;
#pragma unroll
        for (int o = 1; o < 32; o <<= 1) {
            unsigned nb = __shfl_up_sync(0xffffffffu, x, o);
            if (lane >= o) x += nb;
        }
        if (lane < pwarps) red1[pbw + lane] = x;
    }
    NBAR(barid, pthreads);
    unsigned excl = ((gw > pbw) ? red1[gw - 1] : 0u) + (ws - c);
    unsigned mtot = red1[pbw + pwarps - 1];   // strictly greater, < TOPK

    // compact strictly-greater into keys[] (ascending index order preserved)
    unsigned pos = excl;
#pragma unroll
    for (int k = 0; k < 23; ++k) {
        if (k < per) {
            int i = ptid + k * pthreads;
            if (i < cnt && v[k] > tau) {
                unsigned slot = (unsigned)(L * TOPK) + pos;
                keys[slot] = ((unsigned long long)v[k] << 32)
                           | ((4095u - slot) << 15) | (unsigned)(offs + i);
                pos++;
            }
        }
    }
    NBAR(barid, pthreads);

    // tie-fill: remaining slots get == tau entries in ascending index order
    int r = TOPK - (int)mtot;
    int last = -1;
    for (int rep = 0; rep < r; ++rep) {
        unsigned lm = 0xFFFFFFFFu;
#pragma unroll
        for (int k = 0; k < 23; ++k) {
            if (k < per) {
                int i = ptid + k * pthreads;
                if (i < cnt && i > last && v[k] == tau) lm = min(lm, (unsigned)i);
            }
        }
#pragma unroll
        for (int o = 16; o; o >>= 1) lm = min(lm, __shfl_down_sync(0xffffffffu, lm, o));
        if (lane == 0) red2[gw] = lm;
        NBAR(barid, pthreads);
        if (gw == pbw) {
            unsigned s2 = (lane < pwarps) ? red2[pbw + lane] : 0xFFFFFFFFu;
#pragma unroll
            for (int o = 16; o; o >>= 1) s2 = min(s2, __shfl_down_sync(0xffffffffu, s2, o));
            if (lane == 0) sF[L] = s2;
        }
        NBAR(barid, pthreads);
        int found = (int)sF[L];
        if (ptid == 0 && found >= 0 && found < cnt) {
            unsigned slot = (unsigned)(L * TOPK + (int)mtot + rep);
            keys[slot] = ((unsigned long long)tau << 32)
                       | ((4095u - slot) << 15) | (unsigned)(offs + found);
        }
        last = found;
    }

    __syncthreads();   // all partitions done; keys[0..4095] complete

    // ======== PHASE B: bitonic sort (descending), 4 elems/thread ========
    int i0 = tid << 2;
    unsigned long long rr[4];
#pragma unroll
    for (int s = 0; s < 4; ++s) rr[s] = keys[i0 + s];
    __syncthreads();   // everyone loaded before sk overwrites keys

    for (int k = 2; k <= SORTN; k <<= 1) {
        for (int j = k >> 1; j > 0; j >>= 1) {
            if (j >= 128) {
                sk[i0] = rr[0]; sk[i0 + 1] = rr[1]; sk[i0 + 2] = rr[2]; sk[i0 + 3] = rr[3];
                __syncthreads();
                int pb = i0 ^ j;
                bool takeMax = (((i0 & k) == 0) != ((i0 & j) != 0));
#pragma unroll
                for (int s = 0; s < 4; ++s) {
                    unsigned long long p = sk[pb + s];
                    rr[s] = takeMax ? u64max(rr[s], p) : u64min(rr[s], p);
                }
                __syncthreads();
            } else if (j >= 4) {
                int lx = j >> 2;
                bool takeMax = (((i0 & k) == 0) != ((i0 & j) != 0));
#pragma unroll
                for (int s = 0; s < 4; ++s) {
                    unsigned long long p = __shfl_xor_sync(0xffffffffu, rr[s], lx);
                    rr[s] = takeMax ? u64max(rr[s], p) : u64min(rr[s], p);
                }
            } else if (j == 2) {
                cswap(rr[0], rr[2], ((i0    ) & k) == 0);
                cswap(rr[1], rr[3], ((i0 + 1) & k) == 0);
            } else {
                cswap(rr[0], rr[1], ((i0    ) & k) == 0);
                cswap(rr[2], rr[3], ((i0 + 2) & k) == 0);
            }
        }
    }

    // ======== PHASE C: chunked bitmask NMS (R8-proven structure) ========
    for (int cb = 0; cb < NCAND; cb += CH) {
#pragma unroll
        for (int s = 0; s < 4; ++s) {
            int rank = i0 + s;
            if (rank >= cb && rank < cb + CH) ckey[rank - cb] = rr[s];
        }
        __syncthreads();

        bool valid = false;
        if (tid < CH) {
            unsigned long long key = ckey[tid];
            float scf = __uint_as_float((unsigned)(key >> 32));
            valid = (scf > MIN_SC);
            if (valid) {
                int n = (int)((unsigned)key & 0x7FFFu);
                const float *reg, *anc;
                int local, cnt2;
                if (n < N0)        { reg = reg0; anc = anc0; local = n;        cnt2 = N0; }
                else if (n < OFF2) { reg = reg1; anc = anc1; local = n - OFF1; cnt2 = N1; }
                else               { reg = reg2; anc = anc2; local = n - OFF2; cnt2 = N2; }
                size_t base = (size_t)b * cnt2 + local;

                float4 rg = __ldg(reinterpret_cast<const float4*>(reg + base * 4));
                const float* ap = anc + base * 5;
                float ax = __ldg(ap),     ay = __ldg(ap + 1);
                float aw = __ldg(ap + 2), ah = __ldg(ap + 3);
                float st = __ldg(ap + 4);

                float cx = __fmul_rn(__fadd_rn(sigm(rg.x), ax), st);
                float cy = __fmul_rn(__fadd_rn(sigm(rg.y), ay), st);
                float w  = __fdiv_rn(__fmul_rn(expf(rg.z), aw), st);
                float h  = __fdiv_rn(__fmul_rn(expf(rg.w), ah), st);
                float x1 = __fsub_rn(cx, __fmul_rn(0.5f, w));
                float y1 = __fsub_rn(cy, __fmul_rn(0.5f, h));
                float x2 = __fadd_rn(w, x1);
                float y2 = __fadd_rn(h, y1);

                cx1[tid] = max((int)x1, 0);
                cy1[tid] = max((int)y1, 0);
                cx2[tid] = min((int)x2, IMGMAX);
                cy2[tid] = min((int)y2, IMGMAX);
            }
            unsigned bal = __ballot_sync(0xffffffffu, valid);
            if ((tid & 31) == 0) limw[tid >> 5] = __popc(bal);
        }
        __syncthreads();
        if (tid == 0) {
            int lim = 0;
#pragma unroll
            for (int wq = 0; wq < CW; ++wq) lim += (int)limw[wq];
            s_limit = lim;
        }
        __syncthreads();
        int limit = s_limit;
        int kept0 = s_kept;

        // suppression vs previously kept boxes (k2 uniform -> broadcast)
        if (tid < CH) {
            bool sup = false;
            if (tid < limit) {
                int x1 = cx1[tid], y1 = cy1[tid], x2 = cx2[tid], y2 = cy2[tid];
                int ar = (x2 - x1) * (y2 - y1);
                for (int k2 = 0; k2 < kept0; ++k2) {
                    int p1 = kp1[k2], p2 = kp2[k2];
                    int qx1 = p1 & 0xFFFF, qy1 = p1 >> 16;
                    int qx2 = p2 & 0xFFFF, qy2 = p2 >> 16;
                    int iw = min(x2, qx2) - max(x1, qx1);
                    int ih = min(y2, qy2) - max(y1, qy1);
                    if (iw > 0 && ih > 0) {
                        int inter = iw * ih;
                        if (3 * inter > ar + (qx2 - qx1) * (qy2 - qy1)) sup = true;
                    }
                }
            }
            unsigned bal = __ballot_sync(0xffffffffu, sup);
            if ((tid & 31) == 0) supv[tid >> 5] = bal;
        }
        __syncthreads();

        // within-chunk matrix: lanes consecutive i, w uniform -> broadcast j loads
        for (int task = tid; task < CH * CW; task += 1024) {
            int w = task >> 9;
            int i = task & (CH - 1);
            unsigned bits = 0u;
            int jbase = w << 5;
            if (i < limit && jbase + 31 > i) {
                int x1 = cx1[i], y1 = cy1[i], x2 = cx2[i], y2 = cy2[i];
                int ar = (x2 - x1) * (y2 - y1);
                int jmax = min(jbase + 32, limit);
#pragma unroll 4
                for (int j = jbase; j < jmax; ++j) {
                    if (j > i) {
                        int iw = min(x2, cx2[j]) - max(x1, cx1[j]);
                        int ih = min(y2, cy2[j]) - max(y1, cy1[j]);
                        if (iw > 0 && ih > 0) {
                            int inter = iw * ih;
                            if (3 * inter > ar + (cx2[j] - cx1[j]) * (cy2[j] - cy1[j]))
                                bits |= (1u << (j - jbase));
                        }
                    }
                }
            }
            Mw[(i << 4) + w] = bits;
        }
        __syncthreads();

        // warp-0 bitmask DP: one iteration per KEPT box
        if (tid < 32) {
            int kept = kept0;
            unsigned alive = 0u;
            if (tid < CW) {
                int lo2 = tid << 5;
                unsigned vm = (limit <= lo2) ? 0u
                            : ((limit >= lo2 + 32) ? 0xFFFFFFFFu : ((1u << (limit - lo2)) - 1u));
                alive = vm & ~supv[tid];
            }
            while (kept < MAXDET) {
                int c2 = alive ? ((tid << 5) + __ffs(alive) - 1) : 0x7FFFFFFF;
#pragma unroll
                for (int o = 16; o; o >>= 1) c2 = min(c2, __shfl_xor_sync(0xffffffffu, c2, o));
                if (c2 == 0x7FFFFFFF) break;
                if (tid == 0) {
                    kp1[kept] = cx1[c2] | (cy1[c2] << 16);
                    kp2[kept] = cx2[c2] | (cy2[c2] << 16);
                    unsigned long long key = ckey[c2];
                    ksc[kept] = __uint_as_float((unsigned)(key >> 32));
                    kn[kept]  = (int)((unsigned)key & 0x7FFFu);
                }
                kept++;
                unsigned supbits = (tid < CW) ? Mw[(c2 << 4) + tid] : 0u;
                alive &= ~supbits;
                if (tid == (c2 >> 5)) alive &= ~(1u << (c2 & 31));
                __syncwarp();
            }
            if (tid == 0) {
                s_kept = kept;
                s_done = (kept >= MAXDET) || (limit < CH);
            }
        }
        __syncthreads();
        if (s_done) break;
        __syncthreads();
    }

    // ---- outputs (parallel) ----
    int nk = s_kept;
    const int* gcls = g_cls + b * NTOT;
    for (int k = tid; k < MAXDET; k += 1024) {
        float osc = -1.0f, ocl = -1.0f, ox1 = -1.0f, oy1 = -1.0f, ox2 = -1.0f, oy2 = -1.0f;
        if (k < nk) {
            osc = ksc[k];
            ocl = (float)__ldg(gcls + kn[k]);
            int p1 = kp1[k], p2 = kp2[k];
            ox1 = (float)(p1 & 0xFFFF); oy1 = (float)(p1 >> 16);
            ox2 = (float)(p2 & 0xFFFF); oy2 = (float)(p2 >> 16);
        }
        out[b * MAXDET + k] = osc;
        out[BATCH * MAXDET + b * MAXDET + k] = ocl;
        int ob = 2 * BATCH * MAXDET + (b * MAXDET + k) * 4;
        out[ob] = ox1; out[ob + 1] = oy1; out[ob + 2] = ox2; out[ob + 3] = oy2;
    }
}

// ---------------- launcher ----------------
extern "C" void kernel_launch(void* const* d_in, const int* in_sizes, int n_in,
                              void* d_out, int out_size)
{
    (void)out_size;
    static const int dictSizes[12] = {  8664,  34656,   693120,  43320,
                                       34656, 138624,  2772480, 173280,
                                      138624, 554496, 11089920, 693120 };
    static const int sigSizes[12]  = {  8664,  34656, 138624,
                                       34656, 138624, 554496,
                                      693120, 2772480, 11089920,
                                       43320, 173280, 693120 };
    bool isDict = (n_in >= 12), isSig = (n_in >= 12);
    for (int i = 0; i < 12 && i < n_in; i++) {
        if (in_sizes[i] != dictSizes[i]) isDict = false;
        if (in_sizes[i] != sigSizes[i])  isSig  = false;
    }

    // canonical: [0..2]=obj, [3..5]=reg, [6..8]=cls, [9..11]=anchors
    const float* in[12];
    if (isSig && !isDict) {
        for (int i = 0; i < 12; i++) in[i] = (const float*)d_in[i];
    } else {
        for (int l = 0; l < 3; l++) {
            in[l]     = (const float*)d_in[4 * l + 0];
            in[3 + l] = (const float*)d_in[4 * l + 1];
            in[6 + l] = (const float*)d_in[4 * l + 2];
            in[9 + l] = (const float*)d_in[4 * l + 3];
        }
    }

    cudaFuncSetAttribute(topk_sortnms_kernel,
                         cudaFuncAttributeMaxDynamicSharedMemorySize, DSMEM);

    int nthreads = BATCH * NTOT * 4;
    decode_kernel<<<(nthreads + 255) / 256, 256>>>(
        in[0], in[6], in[1], in[7], in[2], in[8]);

    topk_sortnms_kernel<<<BATCH, 1024, DSMEM>>>(in[3], in[9], in[4], in[10], in[5], in[11],
                                                (float*)d_out);
}